// round 8
// baseline (speedup 1.0000x reference)
#include <cuda_runtime.h>
#include <cstdint>

// Problem constants
#define Bb 512
#define Tt 512
#define Ff 32
#define Hh 128
#define Ll 5
#define G4 512          // total gate rows (4H)
#define ROWS 4          // batch rows per CTA
#define K2T 80          // (H+F)/2 total packed k-pairs (k2 0..63 = W_hh, 64..79 = W_ih)
#define K2Q 20          // k-pairs per k-quarter
#define NTHREADS 512

// ---------------- smem layout ----------------
struct __align__(16) Smem {
    float2 wsm[4][K2Q][2][128];  // 163840 B: smem weights; wsm[kq][kk][j][g0] = row g0+256+128j
    float2 hx[K2T][ROWS];        // 2560 B: hx[k2][r]; k<128 -> h, k>=128 -> x_t
    float  red[4][ROWS][G4];     // 32768 B: per-k-quarter partial sums
    float  bias[G4];             // 2048 B: b_ih + b_hh
};
// total 201,216 B (dynamic smem)

// packed f32x2 FMA (Blackwell)
__device__ __forceinline__ unsigned long long ffma2(unsigned long long a,
                                                    unsigned long long b,
                                                    unsigned long long c) {
    unsigned long long d;
    asm("fma.rn.f32x2 %0, %1, %2, %3;" : "=l"(d) : "l"(a), "l"(b), "l"(c));
    return d;
}
__device__ __forceinline__ float hsum2(unsigned long long a) {
    float2 v = *reinterpret_cast<float2*>(&a);
    return v.x + v.y;
}
__device__ __forceinline__ float sigf(float v) {
    return __fdividef(1.f, 1.f + __expf(-v));
}
__device__ __forceinline__ float tanh_fast(float v) {
    float a = fabsf(v);
    float e = __expf(-2.f * a);
    float r = __fdividef(1.f - e, 1.f + e);
    return copysignf(r, v);
}

// ---------------- kernel ----------------
// 128 CTAs x 512 threads. CTA b owns batch rows [4b, 4b+4) and all 512 gate rows.
// Thread t: k-quarter kq = t>>7 (20 k2), gate set {g0, g0+128, g0+256, g0+384},
// g0 = t&127. Gates g0 and g0+128: weights in 40 f32x2 REGISTERS. Gates g0+256,
// g0+384: weights from smem (conflict-free LDS.64). Per step (2 syncs):
//   GEMM: 20 iters x (2 broadcast LDS.128 h + 2 LDS.64 w + 16 FFMA2)
//   each k-quarter writes 16 partials to red[kq]; sync;
//   update: 1 (row,col) item per thread sums 4 quarters x 4 gates + bias,
//   c in a register, h -> hx; sync.
__global__ void __launch_bounds__(NTHREADS, 1)
lstm_kernel(const float* __restrict__ x,
            const float* __restrict__ W_ih,
            const float* __restrict__ W_hh,
            const float* __restrict__ b_ih,
            const float* __restrict__ b_hh,
            const float* __restrict__ W_fc,
            const float* __restrict__ b_fc,
            float* __restrict__ out)
{
    extern __shared__ unsigned char smem_raw[];
    Smem* s = reinterpret_cast<Smem*>(smem_raw);
    const int tid  = threadIdx.x;
    const int kq   = tid >> 7;          // k-quarter: k2 in [20*kq, 20*kq+20)
    const int g0   = tid & 127;         // base gate row
    const int row0 = blockIdx.x * ROWS;

    // ---- prologue: gates g0,g0+128 k-quarter -> regs; g0+256,g0+384 -> smem ----
    const float2* whh2 = reinterpret_cast<const float2*>(W_hh);   // row g: 64 float2
    const float2* wih2 = reinterpret_cast<const float2*>(W_ih);   // row g: 16 float2
    unsigned long long Wr0[K2Q], Wr1[K2Q];
    {
        const int base = kq * K2Q;
        #pragma unroll
        for (int kk = 0; kk < K2Q; ++kk) {
            int k2 = base + kk;
            float2 v0 = (k2 < 64) ? __ldg(whh2 + (size_t)g0 * 64 + k2)
                                  : __ldg(wih2 + (size_t)g0 * 16 + (k2 - 64));
            Wr0[kk] = *reinterpret_cast<unsigned long long*>(&v0);
            float2 v1 = (k2 < 64) ? __ldg(whh2 + (size_t)(g0 + 128) * 64 + k2)
                                  : __ldg(wih2 + (size_t)(g0 + 128) * 16 + (k2 - 64));
            Wr1[kk] = *reinterpret_cast<unsigned long long*>(&v1);
            float2 v2 = (k2 < 64) ? __ldg(whh2 + (size_t)(g0 + 256) * 64 + k2)
                                  : __ldg(wih2 + (size_t)(g0 + 256) * 16 + (k2 - 64));
            s->wsm[kq][kk][0][g0] = v2;
            float2 v3 = (k2 < 64) ? __ldg(whh2 + (size_t)(g0 + 384) * 64 + k2)
                                  : __ldg(wih2 + (size_t)(g0 + 384) * 16 + (k2 - 64));
            s->wsm[kq][kk][1][g0] = v3;
        }
    }
    // bias table (added once, in the update phase)
    if (tid < G4) s->bias[tid] = b_ih[tid] + b_hh[tid];

    // ---- init state: zero h region (k2 0..63), x(t=0) into k2 64..79 ----
    if (tid < 256) s->hx[tid >> 2][tid & 3] = make_float2(0.f, 0.f);
    const int xr = (tid >> 5) & 3, xf = tid & 31;          // loader role for tid<128
    const float* xptr = x + (size_t)(row0 + xr) * Tt * Ff + xf;
    if (tid < 128) {
        float v = __ldg(xptr);
        reinterpret_cast<float*>(&s->hx[64 + (xf >> 1)][xr])[xf & 1] = v;
    }
    __syncthreads();

    // ---- update-phase roles (independent of GEMM roles) ----
    const int ur = tid >> 7;            // batch row of my update item
    const int uj = tid & 127;           // h column of my update item
    float c_ = 0.f;

    const unsigned long long* hq =
        reinterpret_cast<const unsigned long long*>(&s->hx[kq * K2Q][0]);
    const unsigned long long* wp =
        reinterpret_cast<const unsigned long long*>(&s->wsm[kq][0][0][g0]);
    float* redw = &s->red[kq][0][g0];                 // my red write base
    const float* redr = &s->red[0][ur][uj];           // my red read base

    for (int st = 0; st < Tt; ++st) {
        // prefetch next x slice (tid<128)
        float xnext = 0.f;
        if (tid < 128 && st + 1 < Tt) xnext = __ldg(xptr + (size_t)(st + 1) * Ff);

        // ---- GEMM: 4 gates x 4 batch rows, my k-quarter ----
        unsigned long long a0[ROWS], a1[ROWS], a2[ROWS], a3[ROWS];
        #pragma unroll
        for (int r = 0; r < ROWS; ++r) { a0[r] = 0ull; a1[r] = 0ull; a2[r] = 0ull; a3[r] = 0ull; }
        #pragma unroll
        for (int kk = 0; kk < K2Q; ++kk) {
            ulonglong2 hAB = *reinterpret_cast<const ulonglong2*>(hq + kk * 4);     // rows 0,1
            ulonglong2 hCD = *reinterpret_cast<const ulonglong2*>(hq + kk * 4 + 2); // rows 2,3
            unsigned long long w0 = Wr0[kk];
            unsigned long long w1 = Wr1[kk];
            unsigned long long w2 = wp[(size_t)kk * 256];        // wsm[kq][kk][0][g0]
            unsigned long long w3 = wp[(size_t)kk * 256 + 128];  // wsm[kq][kk][1][g0]
            a0[0] = ffma2(hAB.x, w0, a0[0]); a0[1] = ffma2(hAB.y, w0, a0[1]);
            a0[2] = ffma2(hCD.x, w0, a0[2]); a0[3] = ffma2(hCD.y, w0, a0[3]);
            a1[0] = ffma2(hAB.x, w1, a1[0]); a1[1] = ffma2(hAB.y, w1, a1[1]);
            a1[2] = ffma2(hCD.x, w1, a1[2]); a1[3] = ffma2(hCD.y, w1, a1[3]);
            a2[0] = ffma2(hAB.x, w2, a2[0]); a2[1] = ffma2(hAB.y, w2, a2[1]);
            a2[2] = ffma2(hCD.x, w2, a2[2]); a2[3] = ffma2(hCD.y, w2, a2[3]);
            a3[0] = ffma2(hAB.x, w3, a3[0]); a3[1] = ffma2(hAB.y, w3, a3[1]);
            a3[2] = ffma2(hCD.x, w3, a3[2]); a3[3] = ffma2(hCD.y, w3, a3[3]);
        }

        // ---- write 16 partials to my k-quarter's red slab ----
        #pragma unroll
        for (int r = 0; r < ROWS; ++r) {
            redw[r * G4]       = hsum2(a0[r]);
            redw[r * G4 + 128] = hsum2(a1[r]);
            redw[r * G4 + 256] = hsum2(a2[r]);
            redw[r * G4 + 384] = hsum2(a3[r]);
        }
        __syncthreads();

        // ---- h/c update: one (row, col) item per thread, sums 4 k-quarters ----
        {
            const int QS = ROWS * G4;  // red k-quarter stride (floats)
            float iv = ((redr[0*QS]       + redr[1*QS])       + redr[2*QS])       + redr[3*QS]       + s->bias[uj];
            float fv = ((redr[0*QS + 128] + redr[1*QS + 128]) + redr[2*QS + 128]) + redr[3*QS + 128] + s->bias[uj + 128];
            float gv = ((redr[0*QS + 256] + redr[1*QS + 256]) + redr[2*QS + 256]) + redr[3*QS + 256] + s->bias[uj + 256];
            float ov = ((redr[0*QS + 384] + redr[1*QS + 384]) + redr[2*QS + 384]) + redr[3*QS + 384] + s->bias[uj + 384];
            float c = sigf(fv) * c_ + sigf(iv) * tanh_fast(gv);
            c_ = c;
            float h = sigf(ov) * tanh_fast(c);
            reinterpret_cast<float*>(&s->hx[uj >> 1][ur])[uj & 1] = h;
        }
        if (tid < 128 && st + 1 < Tt)
            reinterpret_cast<float*>(&s->hx[64 + (xf >> 1)][xr])[xf & 1] = xnext;
        __syncthreads();
    }

    // ---- FC head on final h ----
    if (tid < ROWS * Ll) {
        int r = tid / Ll, l = tid - r * Ll;
        float acc = b_fc[l];
        const float* wl = W_fc + l * Hh;
        #pragma unroll 16
        for (int k = 0; k < Hh; ++k)
            acc += reinterpret_cast<const float*>(&s->hx[k >> 1][r])[k & 1] * wl[k];
        out[(row0 + r) * Ll + l] = acc;
    }
}

// ---------------- host launch ----------------
extern "C" void kernel_launch(void* const* d_in, const int* in_sizes, int n_in,
                              void* d_out, int out_size) {
    const float* x    = (const float*)d_in[0];
    const float* W_ih = (const float*)d_in[1];
    const float* W_hh = (const float*)d_in[2];
    const float* b_ih = (const float*)d_in[3];
    const float* b_hh = (const float*)d_in[4];
    const float* W_fc = (const float*)d_in[5];
    const float* b_fc = (const float*)d_in[6];
    float* out = (float*)d_out;

    const size_t smem = sizeof(Smem);
    cudaFuncSetAttribute(lstm_kernel, cudaFuncAttributeMaxDynamicSharedMemorySize, (int)smem);
    lstm_kernel<<<Bb / ROWS, NTHREADS, smem>>>(x, W_ih, W_hh, b_ih, b_hh, W_fc, b_fc, out);
}

// round 10
// speedup vs baseline: 1.1057x; 1.1057x over previous
#include <cuda_runtime.h>
#include <cstdint>

// Problem constants
#define Bb 512
#define Tt 512
#define Ff 32
#define Hh 128
#define Ll 5
#define G4 512          // total gate rows (4H)
#define ROWS 4          // batch rows per CTA
#define K2T 80          // (H+F)/2 total packed k-pairs (k2 0..63 = W_hh, 64..79 = W_ih)
#define K2Q 20          // k-pairs per k-quarter
#define KREG 17         // reg-resident k-pairs per register gate
#define KSM  3          // smem tail k-pairs per register gate (K2Q - KREG)
#define NTHREADS 512

// ---------------- smem layout ----------------
struct __align__(16) Smem {
    float2 wlo[4][K2Q][2][128];  // 163840 B: smem gates (g0+256, g0+384): [kq][kk][j][g0]
    float2 whi[4][KSM][2][128];  // 24576 B: reg-gates' tail k2 (g0, g0+128): [kq][kk-KREG][j][g0]
    float2 hx[K2T][ROWS];        // 2560 B: hx[k2][r]; k<128 -> h, k>=128 -> x_t
    float  red[4][ROWS][G4];     // 32768 B: per-k-quarter partial sums (kq0 carries bias)
};
// total 223,744 B (dynamic smem)

// packed f32x2 FMA (Blackwell)
__device__ __forceinline__ unsigned long long ffma2(unsigned long long a,
                                                    unsigned long long b,
                                                    unsigned long long c) {
    unsigned long long d;
    asm("fma.rn.f32x2 %0, %1, %2, %3;" : "=l"(d) : "l"(a), "l"(b), "l"(c));
    return d;
}
__device__ __forceinline__ float hsum2(unsigned long long a) {
    float2 v = *reinterpret_cast<float2*>(&a);
    return v.x + v.y;
}
__device__ __forceinline__ float sigf(float v) {
    return __fdividef(1.f, 1.f + __expf(-v));
}
__device__ __forceinline__ float tanh_fast(float v) {
    float a = fabsf(v);
    float e = __expf(-2.f * a);
    float r = __fdividef(1.f - e, 1.f + e);
    return copysignf(r, v);
}

// ---------------- kernel ----------------
// 128 CTAs x 512 threads. CTA b owns batch rows [4b, 4b+4) and all 512 gate rows.
// Thread t: k-quarter kq = t>>7 (20 k2), gates {g0, g0+128, g0+256, g0+384}.
// Gates g0, g0+128: 17 of 20 k2 in REGISTERS (68 regs), 3 k2 from smem.
// Gates g0+256, g0+384: all 20 k2 from smem (conflict-free LDS.64).
// Per step (2 syncs): GEMM 20 iters x (2 broadcast LDS.128 h + 2-4 LDS.64 w +
// 16 FFMA2); kq writes 16 bias-folded partials to red[kq]; sync; update sums
// 4 quarters x 4 gates, c in a register, h -> hx; sync.
__global__ void __launch_bounds__(NTHREADS, 1)
lstm_kernel(const float* __restrict__ x,
            const float* __restrict__ W_ih,
            const float* __restrict__ W_hh,
            const float* __restrict__ b_ih,
            const float* __restrict__ b_hh,
            const float* __restrict__ W_fc,
            const float* __restrict__ b_fc,
            float* __restrict__ out)
{
    extern __shared__ unsigned char smem_raw[];
    Smem* s = reinterpret_cast<Smem*>(smem_raw);
    const int tid  = threadIdx.x;
    const int kq   = tid >> 7;          // k-quarter: k2 in [20*kq, 20*kq+20)
    const int g0   = tid & 127;         // base gate row
    const int row0 = blockIdx.x * ROWS;

    // ---- prologue: weights -> regs (g0,g0+128 first 17 k2) and smem ----
    const float2* whh2 = reinterpret_cast<const float2*>(W_hh);   // row g: 64 float2
    const float2* wih2 = reinterpret_cast<const float2*>(W_ih);   // row g: 16 float2
    unsigned long long Wr0[KREG], Wr1[KREG];
    {
        const int base = kq * K2Q;
        #pragma unroll
        for (int kk = 0; kk < K2Q; ++kk) {
            int k2 = base + kk;
            float2 v0 = (k2 < 64) ? __ldg(whh2 + (size_t)g0 * 64 + k2)
                                  : __ldg(wih2 + (size_t)g0 * 16 + (k2 - 64));
            float2 v1 = (k2 < 64) ? __ldg(whh2 + (size_t)(g0 + 128) * 64 + k2)
                                  : __ldg(wih2 + (size_t)(g0 + 128) * 16 + (k2 - 64));
            if (kk < KREG) {
                Wr0[kk] = *reinterpret_cast<unsigned long long*>(&v0);
                Wr1[kk] = *reinterpret_cast<unsigned long long*>(&v1);
            } else {
                s->whi[kq][kk - KREG][0][g0] = v0;
                s->whi[kq][kk - KREG][1][g0] = v1;
            }
            float2 v2 = (k2 < 64) ? __ldg(whh2 + (size_t)(g0 + 256) * 64 + k2)
                                  : __ldg(wih2 + (size_t)(g0 + 256) * 16 + (k2 - 64));
            s->wlo[kq][kk][0][g0] = v2;
            float2 v3 = (k2 < 64) ? __ldg(whh2 + (size_t)(g0 + 384) * 64 + k2)
                                  : __ldg(wih2 + (size_t)(g0 + 384) * 16 + (k2 - 64));
            s->wlo[kq][kk][1][g0] = v3;
        }
    }
    // bias folded into kq0's partials only (4 regs)
    float cb[4] = {0.f, 0.f, 0.f, 0.f};
    if (kq == 0) {
        #pragma unroll
        for (int j = 0; j < 4; ++j)
            cb[j] = b_ih[g0 + 128 * j] + b_hh[g0 + 128 * j];
    }

    // ---- init state: zero h region (k2 0..63), x(t=0) into k2 64..79 ----
    if (tid < 256) s->hx[tid >> 2][tid & 3] = make_float2(0.f, 0.f);
    const int xr = (tid >> 5) & 3, xf = tid & 31;          // loader role for tid<128
    const float* xptr = x + (size_t)(row0 + xr) * Tt * Ff + xf;
    if (tid < 128) {
        float v = __ldg(xptr);
        reinterpret_cast<float*>(&s->hx[64 + (xf >> 1)][xr])[xf & 1] = v;
    }
    __syncthreads();

    // ---- update-phase roles (independent of GEMM roles) ----
    const int ur = tid >> 7;            // batch row of my update item
    const int uj = tid & 127;           // h column of my update item
    float c_ = 0.f;

    const unsigned long long* hq =
        reinterpret_cast<const unsigned long long*>(&s->hx[kq * K2Q][0]);
    const unsigned long long* wlo_p =
        reinterpret_cast<const unsigned long long*>(&s->wlo[kq][0][0][g0]);
    const unsigned long long* whi_p =
        reinterpret_cast<const unsigned long long*>(&s->whi[kq][0][0][g0]);
    float* redw = &s->red[kq][0][g0];                 // my red write base
    const float* redr = &s->red[0][ur][uj];           // my red read base

    for (int st = 0; st < Tt; ++st) {
        // prefetch next x slice (tid<128)
        float xnext = 0.f;
        if (tid < 128 && st + 1 < Tt) xnext = __ldg(xptr + (size_t)(st + 1) * Ff);

        // ---- GEMM: 4 gates x 4 batch rows, my k-quarter ----
        unsigned long long a0[ROWS], a1[ROWS], a2[ROWS], a3[ROWS];
        #pragma unroll
        for (int r = 0; r < ROWS; ++r) { a0[r] = 0ull; a1[r] = 0ull; a2[r] = 0ull; a3[r] = 0ull; }
        #pragma unroll
        for (int kk = 0; kk < K2Q; ++kk) {
            ulonglong2 hAB = *reinterpret_cast<const ulonglong2*>(hq + kk * 4);     // rows 0,1
            ulonglong2 hCD = *reinterpret_cast<const ulonglong2*>(hq + kk * 4 + 2); // rows 2,3
            unsigned long long w0 = (kk < KREG) ? Wr0[kk]
                                                : whi_p[(size_t)(kk - KREG) * 256];
            unsigned long long w1 = (kk < KREG) ? Wr1[kk]
                                                : whi_p[(size_t)(kk - KREG) * 256 + 128];
            unsigned long long w2 = wlo_p[(size_t)kk * 256];        // wlo[kq][kk][0][g0]
            unsigned long long w3 = wlo_p[(size_t)kk * 256 + 128];  // wlo[kq][kk][1][g0]
            a0[0] = ffma2(hAB.x, w0, a0[0]); a0[1] = ffma2(hAB.y, w0, a0[1]);
            a0[2] = ffma2(hCD.x, w0, a0[2]); a0[3] = ffma2(hCD.y, w0, a0[3]);
            a1[0] = ffma2(hAB.x, w1, a1[0]); a1[1] = ffma2(hAB.y, w1, a1[1]);
            a1[2] = ffma2(hCD.x, w1, a1[2]); a1[3] = ffma2(hCD.y, w1, a1[3]);
            a2[0] = ffma2(hAB.x, w2, a2[0]); a2[1] = ffma2(hAB.y, w2, a2[1]);
            a2[2] = ffma2(hCD.x, w2, a2[2]); a2[3] = ffma2(hCD.y, w2, a2[3]);
            a3[0] = ffma2(hAB.x, w3, a3[0]); a3[1] = ffma2(hAB.y, w3, a3[1]);
            a3[2] = ffma2(hCD.x, w3, a3[2]); a3[3] = ffma2(hCD.y, w3, a3[3]);
        }

        // ---- write 16 partials (bias folded into kq0) ----
        #pragma unroll
        for (int r = 0; r < ROWS; ++r) {
            redw[r * G4]       = hsum2(a0[r]) + cb[0];
            redw[r * G4 + 128] = hsum2(a1[r]) + cb[1];
            redw[r * G4 + 256] = hsum2(a2[r]) + cb[2];
            redw[r * G4 + 384] = hsum2(a3[r]) + cb[3];
        }
        __syncthreads();

        // ---- h/c update: one (row, col) item per thread, sums 4 k-quarters ----
        {
            const int QS = ROWS * G4;  // red k-quarter stride (floats)
            float iv = ((redr[0*QS]       + redr[1*QS])       + redr[2*QS])       + redr[3*QS];
            float fv = ((redr[0*QS + 128] + redr[1*QS + 128]) + redr[2*QS + 128]) + redr[3*QS + 128];
            float gv = ((redr[0*QS + 256] + redr[1*QS + 256]) + redr[2*QS + 256]) + redr[3*QS + 256];
            float ov = ((redr[0*QS + 384] + redr[1*QS + 384]) + redr[2*QS + 384]) + redr[3*QS + 384];
            float c = sigf(fv) * c_ + sigf(iv) * tanh_fast(gv);
            c_ = c;
            float h = sigf(ov) * tanh_fast(c);
            reinterpret_cast<float*>(&s->hx[uj >> 1][ur])[uj & 1] = h;
        }
        if (tid < 128 && st + 1 < Tt)
            reinterpret_cast<float*>(&s->hx[64 + (xf >> 1)][xr])[xf & 1] = xnext;
        __syncthreads();
    }

    // ---- FC head on final h ----
    if (tid < ROWS * Ll) {
        int r = tid / Ll, l = tid - r * Ll;
        float acc = b_fc[l];
        const float* wl = W_fc + l * Hh;
        #pragma unroll 16
        for (int k = 0; k < Hh; ++k)
            acc += reinterpret_cast<const float*>(&s->hx[k >> 1][r])[k & 1] * wl[k];
        out[(row0 + r) * Ll + l] = acc;
    }
}

// ---------------- host launch ----------------
extern "C" void kernel_launch(void* const* d_in, const int* in_sizes, int n_in,
                              void* d_out, int out_size) {
    const float* x    = (const float*)d_in[0];
    const float* W_ih = (const float*)d_in[1];
    const float* W_hh = (const float*)d_in[2];
    const float* b_ih = (const float*)d_in[3];
    const float* b_hh = (const float*)d_in[4];
    const float* W_fc = (const float*)d_in[5];
    const float* b_fc = (const float*)d_in[6];
    float* out = (float*)d_out;

    const size_t smem = sizeof(Smem);
    cudaFuncSetAttribute(lstm_kernel, cudaFuncAttributeMaxDynamicSharedMemorySize, (int)smem);
    lstm_kernel<<<Bb / ROWS, NTHREADS, smem>>>(x, W_ih, W_hh, b_ih, b_hh, W_fc, b_fc, out);
}